// round 11
// baseline (speedup 1.0000x reference)
#include <cuda_runtime.h>

#define TB 8192   // batch
#define TT 512    // seq len
#define DD 8      // input size
#define HH 64     // hidden
#define R  32     // batch rows per block
#define RP 36     // row stride (floats): 144B
#define NT 256    // threads: u = tid&63 (unit), rg = tid>>6 (row group of 8)

// Gate-interleaved transposed weights WTg[k][u][gate] + interleaved biases.
// Per-layer contiguous: e0=[ih8;hh64]@0, e1@18432, e2@51200,
// d0=[ihx8;ihy64;hh64]@83968, d1@118784, d2@151552, biases@184320.
#define WT_TOTAL 185856
__device__ float g_wt[WT_TOTAL];

struct WSrcs { const float* p[18]; };
__constant__ int c_woff[19] = {0, 2048, 18432, 34816, 51200, 67584, 83968,
                               102400, 118784, 135168, 151552, 167936, 184320,
                               184576, 184832, 185088, 185344, 185600, 185856};

__global__ void transpose_all(WSrcs ws) {
    int idx = blockIdx.x * blockDim.x + threadIdx.x;
    if (idx >= WT_TOTAL) return;
    int seg = 0;
    #pragma unroll
    for (int i = 1; i < 18; i++) seg += (idx >= c_woff[i]);
    int off  = c_woff[seg];
    int cols = (c_woff[seg + 1] - off) >> 8;
    int pos = idx - off;
    int k = pos >> 8, rem = pos & 255, u = rem >> 2, g = rem & 3;
    g_wt[idx] = ws.p[seg][(g * HH + u) * cols + k];
}

__device__ __forceinline__ float tanh_fast(float x) {
    float y;
    asm("tanh.approx.f32 %0, %1;" : "=f"(y) : "f"(x));
    return y;
}
__device__ __forceinline__ float sig_fast(float x) {
    return fmaf(0.5f, tanh_fast(0.5f * x), 0.5f);
}

typedef unsigned long long ull;
__device__ __forceinline__ ull pack2(float w) {
    ull p; asm("mov.b64 %0, {%1, %1};" : "=l"(p) : "f"(w)); return p;
}
__device__ __forceinline__ void fma2(ull& acc, ull a, ull b) {
    asm("fma.rn.f32x2 %0, %1, %2, %0;" : "+l"(acc) : "l"(a), "l"(b));
}
__device__ __forceinline__ void unpack2(ull p, float& lo, float& hi) {
    asm("mov.b64 {%0, %1}, %2;" : "=f"(lo), "=f"(hi) : "l"(p));
}

// warp-pair barrier: pair rg = warps {2rg, 2rg+1}, 64 threads, ids 1..4
__device__ __forceinline__ void pair_bar(int rg) {
    asm volatile("bar.sync %0, 64;" :: "r"(rg + 1) : "memory");
}

// one k: 4 gate weights (in regs) x 8 rows (smem broadcast)
__device__ __forceinline__ void do_k(ull acc[16], float4 w4,
                                     const float* __restrict__ xrow) {
    ull wi = pack2(w4.x), wf = pack2(w4.y);
    ull wg = pack2(w4.z), wo = pack2(w4.w);
    const ulonglong2* xp = (const ulonglong2*)xrow;
    ulonglong2 v01 = xp[0];                 // broadcast LDS.128
    ulonglong2 v23 = xp[1];
    fma2(acc[0],  wi, v01.x); fma2(acc[1],  wi, v01.y);
    fma2(acc[2],  wi, v23.x); fma2(acc[3],  wi, v23.y);
    fma2(acc[4],  wf, v01.x); fma2(acc[5],  wf, v01.y);
    fma2(acc[6],  wf, v23.x); fma2(acc[7],  wf, v23.y);
    fma2(acc[8],  wg, v01.x); fma2(acc[9],  wg, v01.y);
    fma2(acc[10], wg, v23.x); fma2(acc[11], wg, v23.y);
    fma2(acc[12], wo, v01.x); fma2(acc[13], wo, v01.y);
    fma2(acc[14], wo, v23.x); fma2(acc[15], wo, v23.y);
}

// input-row select: k -> buffer A (KA rows), B (KB rows), C (rest)
template<int KA, int KB>
__device__ __forceinline__ const float* selrow(const float* __restrict__ bA,
                                               const float* __restrict__ bB,
                                               const float* __restrict__ bC,
                                               int k) {
    if (k < KA) return bA + k * RP;
    if (k < KA + KB) return bB + (k - KA) * RP;
    return bC + (k - KA - KB) * RP;
}

// Fused gemv over one continuous per-layer weight stream with double-buffered
// weight prefetch. Inputs multiplexed across up to 3 smem buffers.
template<int KA, int KB, int KC>
__device__ __forceinline__ void gemvM(ull acc[16], const float* __restrict__ WTg,
                                      const float* __restrict__ bA,
                                      const float* __restrict__ bB,
                                      const float* __restrict__ bC,
                                      int u, int rg) {
    constexpr int K = KA + KB + KC;
    constexpr int NCH = K / 4;               // 18 / 32 / 34 — always even
    static_assert(NCH % 2 == 0, "chunk count must be even");
    const float* wp = WTg + u * 4;
    const float* pA = bA + rg * 8;
    const float* pB = bB + rg * 8;
    const float* pC = (KC > 0) ? bC + rg * 8 : pA;
    float4 wa[4], wb[4];
    #pragma unroll
    for (int i = 0; i < 4; i++) wa[i] = *(const float4*)(wp + i * 256);
    #pragma unroll 1
    for (int ch = 0; ch < NCH; ch += 2) {
        #pragma unroll
        for (int i = 0; i < 4; i++)          // prefetch chunk ch+1
            wb[i] = *(const float4*)(wp + ((ch + 1) * 4 + i) * 256);
        #pragma unroll
        for (int i = 0; i < 4; i++)          // compute chunk ch
            do_k(acc, wa[i], selrow<KA, KB>(pA, pB, pC, ch * 4 + i));
        if (ch + 2 < NCH) {
            #pragma unroll
            for (int i = 0; i < 4; i++)      // prefetch chunk ch+2
                wa[i] = *(const float4*)(wp + ((ch + 2) * 4 + i) * 256);
        }
        #pragma unroll
        for (int i = 0; i < 4; i++)          // compute chunk ch+1
            do_k(acc, wb[i], selrow<KA, KB>(pA, pB, pC, (ch + 1) * 4 + i));
    }
}

// One LSTM layer step: fused gemv -> state update (c in smem, thread-private)
// -> h store -> pair barrier.
template<int KA, int KB, int KC>
__device__ __forceinline__ void layer_step(const float* __restrict__ WT,
                                           const float* __restrict__ bA,
                                           const float* __restrict__ bB,
                                           const float* __restrict__ bC,
                                           const float* __restrict__ Bint,
                                           float* __restrict__ cbuf,
                                           float* __restrict__ hout,
                                           int u, int rg) {
    ull acc[16];
    {
        float4 b4 = *(const float4*)(Bint + u * 4);
        ull bi = pack2(b4.x), bf = pack2(b4.y), bg = pack2(b4.z), bo = pack2(b4.w);
        acc[0] = acc[1] = acc[2] = acc[3] = bi;
        acc[4] = acc[5] = acc[6] = acc[7] = bf;
        acc[8] = acc[9] = acc[10] = acc[11] = bg;
        acc[12] = acc[13] = acc[14] = acc[15] = bo;
    }
    gemvM<KA, KB, KC>(acc, WT, bA, bB, bC, u, rg);

    float* cb = cbuf + u * RP + rg * 8;      // thread-private c slots
    float4 cv0 = *(float4*)cb;
    float4 cv1 = *(float4*)(cb + 4);
    float cc[8] = {cv0.x, cv0.y, cv0.z, cv0.w, cv1.x, cv1.y, cv1.z, cv1.w};
    float hv[8];
    #pragma unroll
    for (int q = 0; q < 4; q++) {
        float i0, i1, f0, f1, g0, g1, o0, o1;
        unpack2(acc[q],      i0, i1);
        unpack2(acc[4 + q],  f0, f1);
        unpack2(acc[8 + q],  g0, g1);
        unpack2(acc[12 + q], o0, o1);
        float c;
        c = cc[2 * q];
        c = sig_fast(f0) * c + sig_fast(i0) * tanh_fast(g0);
        hv[2 * q] = sig_fast(o0) * tanh_fast(c);
        cc[2 * q] = c;
        c = cc[2 * q + 1];
        c = sig_fast(f1) * c + sig_fast(i1) * tanh_fast(g1);
        hv[2 * q + 1] = sig_fast(o1) * tanh_fast(c);
        cc[2 * q + 1] = c;
    }
    *(float4*)cb       = make_float4(cc[0], cc[1], cc[2], cc[3]);
    *(float4*)(cb + 4) = make_float4(cc[4], cc[5], cc[6], cc[7]);
    float4* hp = (float4*)(hout + u * RP + rg * 8);
    hp[0] = make_float4(hv[0], hv[1], hv[2], hv[3]);
    hp[1] = make_float4(hv[4], hv[5], hv[6], hv[7]);
    pair_bar(rg);
}

#define LSZ (HH * RP)   // 2304 floats

__global__ __launch_bounds__(NT, 2)
void lstm_main(const float* __restrict__ enc_x, const float* __restrict__ dec_x,
               const float* __restrict__ fcW, const float* __restrict__ fcb,
               float* __restrict__ out) {
    extern __shared__ float sm[];
    float* s_h  = sm;                     // [2 parity][3 layer][64][RP]
    float* s_c  = sm + 6 * LSZ;           // [3 layer][64][RP]
    float* s_z  = sm + 9 * LSZ;           // [64][RP] zeros (dec t=0 y_prev)
    float* s_x  = sm + 10 * LSZ;          // [2 parity][8][RP]
    float* s_fc = s_x + 2 * DD * RP;      // 512 fcW^T + 8 fcb

    int tid = threadIdx.x;
    int b0  = blockIdx.x * R;
    int u = tid & 63, rg = tid >> 6;      // gemv tile coords (pair-closed)
    int xr = tid >> 3, xk = tid & 7;      // x staging coords (pair-closed)
    int pr = tid >> 3, pd = tid & 7;      // fc output coords (pair-closed)

    for (int i = tid; i < 10 * LSZ; i += NT) sm[i] = 0.f;   // h, c, zeros
    for (int i = tid; i < DD * HH; i += NT) {
        int uu = i >> 3, d = i & 7;
        s_fc[uu * 8 + d] = fcW[d * HH + uu];
    }
    if (tid < DD) s_fc[512 + tid] = fcb[tid];

    const float* WT_e0 = g_wt;            // [ih8; hh64]
    const float* WT_e1 = g_wt + 18432;    // [ih64; hh64]
    const float* WT_e2 = g_wt + 51200;
    const float* WT_d0 = g_wt + 83968;    // [ihx8; ihy64; hh64]
    const float* WT_d1 = g_wt + 118784;
    const float* WT_d2 = g_wt + 151552;
    const float* B_e0 = g_wt + 184320;    const float* B_e1 = g_wt + 184576;
    const float* B_e2 = g_wt + 184832;    const float* B_d0 = g_wt + 185088;
    const float* B_d1 = g_wt + 185344;    const float* B_d2 = g_wt + 185600;

    const size_t xbase = (size_t)(b0 + xr) * TT * DD + xk;

    // prologue: x(t=0) into parity 0; one block sync publishes init + x
    s_x[xk * RP + xr] = enc_x[xbase];
    __syncthreads();

    // ---------------- encoder (pairs run decoupled from here) ----------------
    for (int t = 0; t < TT; t++) {
        int p = t & 1;
        float* hc = s_h + p * 3 * LSZ;          // write parity
        float* hv = s_h + (p ^ 1) * 3 * LSZ;    // read parity
        const float* sx = s_x + p * DD * RP;
        float xn = (t < TT - 1) ? enc_x[xbase + (size_t)(t + 1) * DD]
                                : dec_x[xbase];
        layer_step<DD, HH, 0>(WT_e0, sx, hv, nullptr,
                              B_e0, s_c, hc, u, rg);
        layer_step<HH, HH, 0>(WT_e1, hc, hv + LSZ, nullptr,
                              B_e1, s_c + LSZ, hc + LSZ, u, rg);
        s_x[(p ^ 1) * DD * RP + xk * RP + xr] = xn;   // ordered by L2's pair bar
        layer_step<HH, HH, 0>(WT_e2, hc + LSZ, hv + 2 * LSZ, nullptr,
                              B_e2, s_c + 2 * LSZ, hc + 2 * LSZ, u, rg);
    }

    // ---------------- decoder ----------------
    for (int t = 0; t < TT; t++) {
        int p = t & 1;
        float* hc = s_h + p * 3 * LSZ;
        float* hv = s_h + (p ^ 1) * 3 * LSZ;
        const float* sx = s_x + p * DD * RP;
        int tn = (t + 1 < TT) ? t + 1 : t;
        float xn = dec_x[xbase + (size_t)tn * DD];
        const float* ybuf = (t > 0) ? (hv + 2 * LSZ) : s_z;   // y_prev (0 at t=0)
        layer_step<DD, HH, HH>(WT_d0, sx, ybuf, hv,
                               B_d0, s_c, hc, u, rg);
        layer_step<HH, HH, 0>(WT_d1, hc, hv + LSZ, nullptr,
                              B_d1, s_c + LSZ, hc + LSZ, u, rg);
        s_x[(p ^ 1) * DD * RP + xk * RP + xr] = xn;
        layer_step<HH, HH, 0>(WT_d2, hc + LSZ, hv + 2 * LSZ, nullptr,
                              B_d2, s_c + 2 * LSZ, hc + 2 * LSZ, u, rg);

        // pred = h2 @ fcW^T + fcb (pair rows; ordered by L2's pair bar)
        const float* h2 = hc + 2 * LSZ;
        float a = s_fc[512 + pd];
        #pragma unroll 8
        for (int uu = 0; uu < HH; uu++)
            a = fmaf(s_fc[uu * 8 + pd], h2[uu * RP + pr], a);
        out[(size_t)(b0 + pr) * TT * DD + t * DD + pd] = a;
    }
}

extern "C" void kernel_launch(void* const* d_in, const int* in_sizes, int n_in,
                              void* d_out, int out_size) {
    const float* enc_x = (const float*)d_in[0];
    const float* dec_x = (const float*)d_in[1];

    WSrcs ws;
    const int src_idx[18] = {2, 3, 5, 6, 8, 9, 11, 12, 14, 15, 17, 18,
                             4, 7, 10, 13, 16, 19};
    for (int i = 0; i < 18; i++) ws.p[i] = (const float*)d_in[src_idx[i]];
    transpose_all<<<(WT_TOTAL + 255) / 256, 256>>>(ws);

    size_t smem = (size_t)(10 * LSZ + 2 * DD * RP + 520) * sizeof(float);
    cudaFuncSetAttribute(lstm_main, cudaFuncAttributeMaxDynamicSharedMemorySize, (int)smem);

    lstm_main<<<TB / R, NT, smem>>>(enc_x, dec_x,
                                    (const float*)d_in[20], (const float*)d_in[21],
                                    (float*)d_out);
}

// round 14
// speedup vs baseline: 1.8103x; 1.8103x over previous
#include <cuda_runtime.h>

#define TB 8192   // batch
#define TT 512    // seq len
#define DD 8      // input size
#define HH 64     // hidden
#define R  32     // batch rows per block
#define RP 36     // row stride (floats): 144B
#define NT 256    // threads: u = tid&63 (unit), rg = tid>>6 (row group of 8)

// Gate-interleaved transposed weights WTg[k][u][gate] + interleaved biases.
// Per-layer contiguous streams: e0=[ih8;hh64]@0, e1=[ih64;hh64]@18432, e2@51200,
// d0=[ihx8;ihy64;hh64]@83968, d1@118784, d2@151552, biases@184320.
#define WT_TOTAL 185856
__device__ float g_wt[WT_TOTAL];

struct WSrcs { const float* p[18]; };
__constant__ int c_woff[19] = {0, 2048, 18432, 34816, 51200, 67584, 83968,
                               102400, 118784, 135168, 151552, 167936, 184320,
                               184576, 184832, 185088, 185344, 185600, 185856};

__global__ void transpose_all(WSrcs ws) {
    int idx = blockIdx.x * blockDim.x + threadIdx.x;
    if (idx >= WT_TOTAL) return;
    int seg = 0;
    #pragma unroll
    for (int i = 1; i < 18; i++) seg += (idx >= c_woff[i]);
    int off  = c_woff[seg];
    int cols = (c_woff[seg + 1] - off) >> 8;
    int pos = idx - off;
    int k = pos >> 8, rem = pos & 255, u = rem >> 2, g = rem & 3;
    g_wt[idx] = ws.p[seg][(g * HH + u) * cols + k];
}

__device__ __forceinline__ float tanh_fast(float x) {
    float y;
    asm("tanh.approx.f32 %0, %1;" : "=f"(y) : "f"(x));
    return y;
}
__device__ __forceinline__ float sig_fast(float x) {
    return fmaf(0.5f, tanh_fast(0.5f * x), 0.5f);
}

typedef unsigned long long ull;
__device__ __forceinline__ ull pack2(float w) {
    ull p; asm("mov.b64 %0, {%1, %1};" : "=l"(p) : "f"(w)); return p;
}
__device__ __forceinline__ void fma2(ull& acc, ull a, ull b) {
    asm("fma.rn.f32x2 %0, %1, %2, %0;" : "+l"(acc) : "l"(a), "l"(b));
}
__device__ __forceinline__ void unpack2(ull p, float& lo, float& hi) {
    asm("mov.b64 {%0, %1}, %2;" : "=f"(lo), "=f"(hi) : "l"(p));
}

// one k: 4 gate weights (in regs) x 8 rows (smem broadcast)
__device__ __forceinline__ void do_k(ull acc[16], float4 w4,
                                     const float* __restrict__ xrow) {
    ull wi = pack2(w4.x), wf = pack2(w4.y);
    ull wg = pack2(w4.z), wo = pack2(w4.w);
    const ulonglong2* xp = (const ulonglong2*)xrow;
    ulonglong2 v01 = xp[0];                 // broadcast LDS.128
    ulonglong2 v23 = xp[1];
    fma2(acc[0],  wi, v01.x); fma2(acc[1],  wi, v01.y);
    fma2(acc[2],  wi, v23.x); fma2(acc[3],  wi, v23.y);
    fma2(acc[4],  wf, v01.x); fma2(acc[5],  wf, v01.y);
    fma2(acc[6],  wf, v23.x); fma2(acc[7],  wf, v23.y);
    fma2(acc[8],  wg, v01.x); fma2(acc[9],  wg, v01.y);
    fma2(acc[10], wg, v23.x); fma2(acc[11], wg, v23.y);
    fma2(acc[12], wo, v01.x); fma2(acc[13], wo, v01.y);
    fma2(acc[14], wo, v23.x); fma2(acc[15], wo, v23.y);
}

// gemv over ONE contiguous input region, double-buffered weight prefetch.
template<int K>
__device__ __forceinline__ void gemvP(ull acc[16], const float* __restrict__ WTg,
                                      const float* __restrict__ buf,
                                      int u, int rg) {
    const float* wp = WTg + u * 4;
    const float* bp = buf + rg * 8;
    float4 wa[4], wb[4];
    #pragma unroll
    for (int i = 0; i < 4; i++) wa[i] = *(const float4*)(wp + i * 256);
    constexpr int NCH = K / 4;               // 2 / 16 / 32 / 34 — always even
    static_assert(NCH % 2 == 0, "even chunk count required");
    #pragma unroll 1
    for (int ch = 0; ch < NCH; ch += 2) {
        #pragma unroll
        for (int i = 0; i < 4; i++)          // prefetch chunk ch+1
            wb[i] = *(const float4*)(wp + ((ch + 1) * 4 + i) * 256);
        #pragma unroll
        for (int i = 0; i < 4; i++)          // compute chunk ch
            do_k(acc, wa[i], bp + (ch * 4 + i) * RP);
        if (ch + 2 < NCH) {
            #pragma unroll
            for (int i = 0; i < 4; i++)      // prefetch chunk ch+2
                wa[i] = *(const float4*)(wp + ((ch + 2) * 4 + i) * 256);
        }
        #pragma unroll
        for (int i = 0; i < 4; i++)          // compute chunk ch+1
            do_k(acc, wb[i], bp + ((ch + 1) * 4 + i) * RP);
    }
}

__device__ __forceinline__ void acc_init(ull acc[16], const float* __restrict__ Bint,
                                         int u) {
    float4 b4 = *(const float4*)(Bint + u * 4);
    ull bi = pack2(b4.x), bf = pack2(b4.y), bg = pack2(b4.z), bo = pack2(b4.w);
    acc[0] = acc[1] = acc[2] = acc[3] = bi;
    acc[4] = acc[5] = acc[6] = acc[7] = bf;
    acc[8] = acc[9] = acc[10] = acc[11] = bg;
    acc[12] = acc[13] = acc[14] = acc[15] = bo;
}

// nonlinearity + state update; optional second h destination (h2 duplication)
__device__ __forceinline__ void update_store(ull acc[16], float* __restrict__ cbuf,
                                             float* __restrict__ hout,
                                             float* __restrict__ hout2,
                                             int u, int rg) {
    float* cb = cbuf + u * RP + rg * 8;      // thread-private c slots
    float4 cv0 = *(float4*)cb;
    float4 cv1 = *(float4*)(cb + 4);
    float cc[8] = {cv0.x, cv0.y, cv0.z, cv0.w, cv1.x, cv1.y, cv1.z, cv1.w};
    float hv[8];
    #pragma unroll
    for (int q = 0; q < 4; q++) {
        float i0, i1, f0, f1, g0, g1, o0, o1;
        unpack2(acc[q],      i0, i1);
        unpack2(acc[4 + q],  f0, f1);
        unpack2(acc[8 + q],  g0, g1);
        unpack2(acc[12 + q], o0, o1);
        float c;
        c = cc[2 * q];
        c = sig_fast(f0) * c + sig_fast(i0) * tanh_fast(g0);
        hv[2 * q] = sig_fast(o0) * tanh_fast(c);
        cc[2 * q] = c;
        c = cc[2 * q + 1];
        c = sig_fast(f1) * c + sig_fast(i1) * tanh_fast(g1);
        hv[2 * q + 1] = sig_fast(o1) * tanh_fast(c);
        cc[2 * q + 1] = c;
    }
    *(float4*)cb       = make_float4(cc[0], cc[1], cc[2], cc[3]);
    *(float4*)(cb + 4) = make_float4(cc[4], cc[5], cc[6], cc[7]);
    float4 h03 = make_float4(hv[0], hv[1], hv[2], hv[3]);
    float4 h47 = make_float4(hv[4], hv[5], hv[6], hv[7]);
    float4* hp = (float4*)(hout + u * RP + rg * 8);
    hp[0] = h03; hp[1] = h47;
    if (hout2) {
        float4* hq = (float4*)(hout2 + u * RP + rg * 8);
        hq[0] = h03; hq[1] = h47;
    }
}

// Parity-interleaved block layout, 264 rows x RP per block, 2 blocks:
//   [X(8) | H2A(64) | H0(64) | H1(64) | H2B(64)]
// Within block s: x parity s, h2a/h0/h2b parity s^1, h1 parity s.
#define LSZ  (HH * RP)        // 2304
#define BROWS 264
#define BSZ  (BROWS * RP)     // 9504
#define OX   0
#define OH2A (8 * RP)
#define OH0  (72 * RP)
#define OH1  (136 * RP)
#define OH2B (200 * RP)

__global__ __launch_bounds__(NT, 2)
void lstm_main(const float* __restrict__ enc_x, const float* __restrict__ dec_x,
               const float* __restrict__ fcW, const float* __restrict__ fcb,
               float* __restrict__ out) {
    extern __shared__ float sm[];
    float* s_c  = sm + 2 * BSZ;           // [3 layer][64][RP]
    float* s_fc = s_c + 3 * LSZ;          // 512 fcW^T + 8 fcb

    int tid = threadIdx.x;
    int b0  = blockIdx.x * R;
    int u = tid & 63, rg = tid >> 6;      // gemv tile coords
    int xr = tid >> 3, xk = tid & 7;      // x staging coords
    int pr = tid >> 3, pd = tid & 7;      // fc output coords

    for (int i = tid; i < 2 * BSZ + 3 * LSZ; i += NT) sm[i] = 0.f;
    for (int i = tid; i < DD * HH; i += NT) {
        int uu = i >> 3, d = i & 7;
        s_fc[uu * 8 + d] = fcW[d * HH + uu];
    }
    if (tid < DD) s_fc[512 + tid] = fcb[tid];

    const float* WT_e0 = g_wt;            // [ih8; hh64]
    const float* WT_e1 = g_wt + 18432;    // [ih64; hh64]
    const float* WT_e2 = g_wt + 51200;
    const float* WT_d0 = g_wt + 83968;    // [ihx8; ihy64; hh64]
    const float* WT_d1 = g_wt + 118784;
    const float* WT_d2 = g_wt + 151552;
    const float* B_e0 = g_wt + 184320;    const float* B_e1 = g_wt + 184576;
    const float* B_e2 = g_wt + 184832;    const float* B_d0 = g_wt + 185088;
    const float* B_d1 = g_wt + 185344;    const float* B_d2 = g_wt + 185600;

    const size_t xbase = (size_t)(b0 + xr) * TT * DD + xk;

    // prologue: x(t=0) into block 0's X region; one sync publishes init + x
    sm[OX + xk * RP + xr] = enc_x[xbase];
    __syncthreads();

    // ---------------- encoder ----------------
    for (int t = 0; t < TT; t++) {
        int p = t & 1;
        float* bp = sm + p * BSZ;               // block p
        float* bq = sm + (p ^ 1) * BSZ;         // block p^1
        float xn = (t < TT - 1) ? enc_x[xbase + (size_t)(t + 1) * DD]
                                : dec_x[xbase];
        {   // L0: x (K=8) + h0_prev (K=64), both in block p (non-adjacent)
            ull acc[16];
            acc_init(acc, B_e0, u);
            gemvP<DD>(acc, WT_e0, bp + OX, u, rg);
            gemvP<HH>(acc, WT_e0 + DD * 256, bp + OH0, u, rg);
            update_store(acc, s_c, bq + OH0, nullptr, u, rg);
            __syncthreads();
        }
        {   // L1: fused [h0_cur; h1_prev] = bq rows 72..199
            ull acc[16];
            acc_init(acc, B_e1, u);
            gemvP<2 * HH>(acc, WT_e1, bq + OH0, u, rg);
            update_store(acc, s_c + LSZ, bp + OH1, nullptr, u, rg);
            __syncthreads();
        }
        bq[OX + xk * RP + xr] = xn;             // stage next x (ordered by L2 sync)
        {   // L2: fused [h1_cur; h2_prev] = bp rows 136..263
            ull acc[16];
            acc_init(acc, B_e2, u);
            gemvP<2 * HH>(acc, WT_e2, bp + OH1, u, rg);
            update_store(acc, s_c + 2 * LSZ, bq + OH2B, nullptr, u, rg);
            __syncthreads();
        }
    }

    // ---------------- decoder ----------------
    // h2a slots still zero from init (encoder never writes them) -> y_prev(t=0)=0
    for (int t = 0; t < TT; t++) {
        int p = t & 1;
        float* bp = sm + p * BSZ;
        float* bq = sm + (p ^ 1) * BSZ;
        int tn = (t + 1 < TT) ? t + 1 : t;
        float xn = dec_x[xbase + (size_t)tn * DD];
        {   // L0: fused [x; y_prev; h0_prev] = bp rows 0..135, K=136
            ull acc[16];
            acc_init(acc, B_d0, u);
            gemvP<DD + 2 * HH>(acc, WT_d0, bp + OX, u, rg);
            update_store(acc, s_c, bq + OH0, nullptr, u, rg);
            __syncthreads();
        }
        {   // L1: fused [h0_cur; h1_prev] = bq rows 72..199
            ull acc[16];
            acc_init(acc, B_d1, u);
            gemvP<2 * HH>(acc, WT_d1, bq + OH0, u, rg);
            update_store(acc, s_c + LSZ, bp + OH1, nullptr, u, rg);
            __syncthreads();
        }
        bq[OX + xk * RP + xr] = xn;
        {   // L2: fused [h1_cur; h2_prev] = bp rows 136..263; dual h2 write
            ull acc[16];
            acc_init(acc, B_d2, u);
            gemvP<2 * HH>(acc, WT_d2, bp + OH1, u, rg);
            update_store(acc, s_c + 2 * LSZ, bq + OH2B, bq + OH2A, u, rg);
            __syncthreads();
        }
        // pred = h2 @ fcW^T + fcb (ordered by L2's sync)
        const float* h2 = bq + OH2B;
        float a = s_fc[512 + pd];
        #pragma unroll 8
        for (int uu = 0; uu < HH; uu++)
            a = fmaf(s_fc[uu * 8 + pd], h2[uu * RP + pr], a);
        out[(size_t)(b0 + pr) * TT * DD + t * DD + pd] = a;
    }
}

extern "C" void kernel_launch(void* const* d_in, const int* in_sizes, int n_in,
                              void* d_out, int out_size) {
    const float* enc_x = (const float*)d_in[0];
    const float* dec_x = (const float*)d_in[1];

    WSrcs ws;
    const int src_idx[18] = {2, 3, 5, 6, 8, 9, 11, 12, 14, 15, 17, 18,
                             4, 7, 10, 13, 16, 19};
    for (int i = 0; i < 18; i++) ws.p[i] = (const float*)d_in[src_idx[i]];
    transpose_all<<<(WT_TOTAL + 255) / 256, 256>>>(ws);

    size_t smem = (size_t)(2 * BSZ + 3 * LSZ + 520) * sizeof(float);
    cudaFuncSetAttribute(lstm_main, cudaFuncAttributeMaxDynamicSharedMemorySize, (int)smem);

    lstm_main<<<TB / R, NT, smem>>>(enc_x, dec_x,
                                    (const float*)d_in[20], (const float*)d_in[21],
                                    (float*)d_out);
}